// round 14
// baseline (speedup 1.0000x reference)
#include <cuda_runtime.h>
#include <cuda_fp16.h>
#include <math.h>

#define BB 8
#define CC 3
#define NF 2
#define H0 512
#define W0 1024

#define L0 (512*1024)
#define L1 (256*512)
#define L2 (128*256)
#define L3 (64*128)

#define PI_F 3.14159265358979323846f

// VP texel (float4): .x=top rg(half2 bits) .y=top bp .z=bottom rg .w=bottom bp
// where bottom = pixel at y+1 (clamped at image bottom)

__device__ __forceinline__ __half2 h2_from_f(float f) {
    __half2 h; *(unsigned*)&h = __float_as_uint(f); return h;
}
__device__ __forceinline__ float f_from_h2(__half2 h) {
    return __uint_as_float(*(unsigned*)&h);
}
__device__ __forceinline__ float2 h2f2(float bits) {
    return __half22float2(h2_from_f(bits));
}

// ---- static device scratch ----
__device__ float g_rr1[BB*CC*L1];
__device__ float g_rr2[BB*CC*L2];
__device__ float g_rr3[BB*CC*L3];
__device__ float4 g_vp0_0[BB*L0];
__device__ float4 g_vp1_0[BB*L0];
__device__ float4 g_vp0_1[BB*L1];
__device__ float4 g_vp1_1[BB*L1];
__device__ float4 g_vp0_2[BB*L2];
__device__ float4 g_vp1_2[BB*L2];
__device__ float4 g_vp0_3[BB*L3];
__device__ float4 g_vp1_3[BB*L3];
__device__ __align__(16) float g_Rt[BB*NF*12];
__device__ float2 g_lon[1920];
__device__ float2 g_lat[960];

__device__ __forceinline__ float2 pack_px(float r, float g, float b) {
    return make_float2(f_from_h2(__floats2half2_rn(r, g)),
                       f_from_h2(__floats2half2_rn(b, 0.0f)));
}
__device__ __forceinline__ float getc(float4 v, int i) {
    switch (i) { case 0: return v.x; case 1: return v.y; case 2: return v.z; default: return v.w; }
}

// ---------------- setup ----------------
__global__ void setup_kernel(const float* __restrict__ pose, float* __restrict__ out) {
    int idx = blockIdx.x * blockDim.x + threadIdx.x;
    if (idx == 0) out[0] = 0.0f;
    if (idx < BB*NF) {
        const float* p = pose + idx*6;
        float tx = p[0], ty = p[1], tz = p[2];
        float rx = p[3], ry = p[4], rz = p[5];
        float th = sqrtf(rx*rx + ry*ry + rz*rz);
        float inv = 1.0f / fmaxf(th, 1e-8f);
        float kx = rx*inv, ky = ry*inv, kz = rz*inv;
        float s = sinf(th), c = cosf(th), mc = 1.0f - c;
        float* R = g_Rt + idx*12;
        R[0] = 1.0f + mc*(-(ky*ky + kz*kz));
        R[1] = -s*kz + mc*(kx*ky);
        R[2] =  s*ky + mc*(kx*kz);
        R[3] =  s*kz + mc*(kx*ky);
        R[4] = 1.0f + mc*(-(kx*kx + kz*kz));
        R[5] = -s*kx + mc*(ky*kz);
        R[6] = -s*ky + mc*(kx*kz);
        R[7] =  s*kx + mc*(ky*kz);
        R[8] = 1.0f + mc*(-(kx*kx + ky*ky));
        R[9] = tx; R[10] = ty; R[11] = tz;
    }
    if (idx < 1920) {
        int off, w;
        if (idx < 1024)      { off = 0;    w = 1024; }
        else if (idx < 1536) { off = 1024; w = 512;  }
        else if (idx < 1792) { off = 1536; w = 256;  }
        else                 { off = 1792; w = 128;  }
        int x = idx - off;
        float lon = (((float)x + 0.5f) / (float)w * 2.0f - 1.0f) * PI_F;
        g_lon[idx] = make_float2(sinf(lon), cosf(lon));
    } else if (idx < 1920 + 960) {
        int i2 = idx - 1920;
        int off, h;
        if (i2 < 512)      { off = 0;   h = 512; }
        else if (i2 < 768) { off = 512; h = 256; }
        else if (i2 < 896) { off = 768; h = 128; }
        else               { off = 896; h = 64;  }
        int y = i2 - off;
        float lat = -((((float)y + 0.5f) / (float)h) * 2.0f - 1.0f) * (0.5f * PI_F);
        g_lat[i2] = make_float2(sinf(lat), cosf(lat));
    }
}

// write one pixel value into the VP image (top of its own row, bottom of row-1,
// and bottom of own row when it is the last row)
__device__ __forceinline__ void vp_write(float4* vp, int W, int H, int x, int y, float2 v) {
    float2* t = (float2*)(vp + (size_t)y*W + x);
    t[0] = v;                                    // top half
    if (y > 0)      ((float2*)(vp + (size_t)(y-1)*W + x))[1] = v;
    if (y == H - 1) t[1] = v;
}

// ---------------- K2: build level0 VP + level1 VP targets + ref level1 ----------------
// blocks [0, 4096): tgt path;  blocks [4096, 16384): ref_lvl1 path
__global__ void build01(const float* __restrict__ t0src, const float* __restrict__ t1src,
                        const float* __restrict__ ref,
                        float4* __restrict__ vp00, float4* __restrict__ vp10,
                        float4* __restrict__ vp01, float4* __restrict__ vp11,
                        float* __restrict__ rr1) {
    int bx = blockIdx.x;
    if (bx < 4096) {
        int z = bx >> 8;
        int b = z >> 1, f = z & 1;
        const float* src = (f ? t1src : t0src) + (size_t)b*CC*L0;
        float4* vp = (f ? vp10 : vp00) + (size_t)b*L0;
        float4* v1 = (f ? vp11 : vp01) + (size_t)b*L1;
        int tid = (bx & 255) * 256 + threadIdx.x;  // < 65536
        int tx = tid & 255;
        int ty = tid >> 8;
        int x0 = tx * 4, y0 = ty * 2;
        int y2c = min(y0 + 2, H0 - 1);

        float4 a0 = *(const float4*)(src + (size_t)0*L0 + (size_t)y0*W0 + x0);
        float4 b0 = *(const float4*)(src + (size_t)1*L0 + (size_t)y0*W0 + x0);
        float4 c0 = *(const float4*)(src + (size_t)2*L0 + (size_t)y0*W0 + x0);
        float4 a1 = *(const float4*)(src + (size_t)0*L0 + (size_t)(y0+1)*W0 + x0);
        float4 b1 = *(const float4*)(src + (size_t)1*L0 + (size_t)(y0+1)*W0 + x0);
        float4 c1 = *(const float4*)(src + (size_t)2*L0 + (size_t)(y0+1)*W0 + x0);
        float4 a2 = *(const float4*)(src + (size_t)0*L0 + (size_t)y2c*W0 + x0);
        float4 b2 = *(const float4*)(src + (size_t)1*L0 + (size_t)y2c*W0 + x0);
        float4 c2 = *(const float4*)(src + (size_t)2*L0 + (size_t)y2c*W0 + x0);

        float4* r0 = vp + (size_t)y0*W0 + x0;
        float4* r1 = vp + (size_t)(y0+1)*W0 + x0;
        #pragma unroll
        for (int i = 0; i < 4; i++) {
            float2 top = pack_px(getc(a0,i), getc(b0,i), getc(c0,i));
            float2 mid = pack_px(getc(a1,i), getc(b1,i), getc(c1,i));
            float2 bot = pack_px(getc(a2,i), getc(b2,i), getc(c2,i));
            r0[i] = make_float4(top.x, top.y, mid.x, mid.y);
            r1[i] = make_float4(mid.x, mid.y, bot.x, bot.y);
        }

        // level1 VP: two pixels at (2tx, ty), (2tx+1, ty)
        float2 p1a = pack_px(0.25f*(a0.x + a0.y + a1.x + a1.y),
                             0.25f*(b0.x + b0.y + b1.x + b1.y),
                             0.25f*(c0.x + c0.y + c1.x + c1.y));
        float2 p1b = pack_px(0.25f*(a0.z + a0.w + a1.z + a1.w),
                             0.25f*(b0.z + b0.w + b1.z + b1.w),
                             0.25f*(c0.z + c0.w + c1.z + c1.w));
        vp_write(v1, 512, 256, tx*2,     ty, p1a);
        vp_write(v1, 512, 256, tx*2 + 1, ty, p1b);
    } else {
        int idx = (bx - 4096) * 256 + threadIdx.x;   // < BB*CC*L1
        const int w2 = 512, w = 1024;
        int img = idx / L1, p = idx % L1;
        int y = p / w2, x = p % w2;
        const float* s = ref + ((size_t)img*512 + y*2) * w + x*2;
        rr1[idx] = 0.25f*(s[0] + s[1] + s[w] + s[w+1]);
    }
}

// ---------------- K3: target levels 2+3 (VP) and ref levels 2+3 ----------------
// blocks [0,512): tgt path (f = bx>>8);  blocks [512, 1280): ref path
__global__ void build23(const float4* __restrict__ vp01, const float4* __restrict__ vp11,
                        float4* __restrict__ vp02, float4* __restrict__ vp12,
                        float4* __restrict__ vp03, float4* __restrict__ vp13,
                        const float* __restrict__ rr1, float* __restrict__ rr2,
                        float* __restrict__ rr3) {
    int bx = blockIdx.x;
    if (bx < 512) {
        int f = bx >> 8;
        int idx = (bx & 255) * 256 + threadIdx.x;     // < BB*L3
        const float4* v1 = (f ? vp11 : vp01);
        float4* v2 = (f ? vp12 : vp02);
        float4* v3 = (f ? vp13 : vp03);
        const int w3 = 128, w2 = 256, w1 = 512;
        int b = idx / L3, p = idx % L3;
        int x3 = p % w3, y3 = p / w3;
        const float4* base1 = v1 + (size_t)b*L1;
        float4* base2 = v2 + (size_t)b*L2;
        float4* base3 = v3 + (size_t)b*L3;

        float3 acc3 = make_float3(0.f, 0.f, 0.f);
        #pragma unroll
        for (int dy = 0; dy < 2; dy++) {
            #pragma unroll
            for (int dx = 0; dx < 2; dx++) {
                int X2 = 2*x3 + dx, Y2 = 2*y3 + dy;
                // VP texels at l1 row 2*Y2 give rows 2*Y2 and 2*Y2+1
                float4 t0 = base1[(size_t)(2*Y2)*w1 + 2*X2];
                float4 t1 = base1[(size_t)(2*Y2)*w1 + 2*X2 + 1];
                float2 a = h2f2(t0.x), ab = h2f2(t0.y);
                float2 c = h2f2(t0.z), cb = h2f2(t0.w);
                float2 e = h2f2(t1.x), eb = h2f2(t1.y);
                float2 g = h2f2(t1.z), gb = h2f2(t1.w);
                float sr = 0.25f*(a.x + c.x + e.x + g.x);
                float sg = 0.25f*(a.y + c.y + e.y + g.y);
                float sb = 0.25f*(ab.x + cb.x + eb.x + gb.x);
                vp_write(base2, w2, 128, X2, Y2, pack_px(sr, sg, sb));
                acc3.x += sr; acc3.y += sg; acc3.z += sb;
            }
        }
        vp_write(base3, w3, 64, x3, y3,
                 pack_px(0.25f*acc3.x, 0.25f*acc3.y, 0.25f*acc3.z));
    } else {
        int idx = (bx - 512) * 256 + threadIdx.x;     // < BB*CC*L3
        const int w3 = 128, w2 = 256, w1 = 512;
        int img = idx / L3, p = idx % L3;
        int x3 = p % w3, y3 = p / w3;
        const float* base1 = rr1 + (size_t)img*L1 + (size_t)(y3*4)*w1 + x3*4;
        float* base2 = rr2 + (size_t)img*L2 + (size_t)(y3*2)*w2 + x3*2;
        float acc = 0.0f;
        #pragma unroll
        for (int dy = 0; dy < 2; dy++) {
            #pragma unroll
            for (int dx = 0; dx < 2; dx++) {
                const float* s = base1 + (size_t)(dy*2)*w1 + dx*2;
                float v = 0.25f*(s[0] + s[1] + s[w1] + s[w1+1]);
                base2[(size_t)dy*w2 + dx] = v;
                acc += v;
            }
        }
        rr3[(size_t)img*L3 + p] = 0.25f*acc;
    }
}

// ---------------- fast atan2, single MUFU divide ----------------
__device__ __forceinline__ float atan_poly(float x) {
    float z = x * x;
    float r = fmaf(8.05374449538e-2f, z, -1.38776856032e-1f);
    r = fmaf(r, z, 1.99777106478e-1f);
    r = fmaf(r, z, -3.33329491539e-1f);
    return fmaf(r * z, x, x);
}
__device__ __forceinline__ float fast_atan2f(float y, float x) {
    float ay = fabsf(y), ax = fabsf(x);
    float mx = fmaxf(ax, ay), mn = fminf(ax, ay);
    bool big = mn > 0.41421356f * mx;
    float num = big ? (mn - mx) : mn;
    float den = big ? (mn + mx) : mx;
    float arg = __fdividef(num, den);
    float r = atan_poly(arg) + (big ? 0.78539816339744831f : 0.0f);
    if (ay > ax) r = 1.57079632679489662f - r;
    if (x < 0.0f) r = PI_F - r;
    return copysignf(r, y);
}
__device__ __forceinline__ float fast_atan2f_pos(float y, float x) {
    float ay = fabsf(y);
    float mx = fmaxf(x, ay), mn = fminf(x, ay);
    bool big = mn > 0.41421356f * mx;
    float num = big ? (mn - mx) : mn;
    float den = big ? (mn + mx) : mx;
    float arg = __fdividef(num, den);
    float r = atan_poly(arg) + (big ? 0.78539816339744831f : 0.0f);
    if (ay > x) r = 1.57079632679489662f - r;
    return copysignf(r, y);
}

template <int W, int H>
__device__ __forceinline__ void project(const float* Rt, float px0, float py0, float pz0,
                                        int& ix0, int& ix1, int& iy0,
                                        float& fx, float& fy) {
    float px = fmaf(Rt[0], px0, fmaf(Rt[1], py0, fmaf(Rt[2], pz0, Rt[9])));
    float py = fmaf(Rt[3], px0, fmaf(Rt[4], py0, fmaf(Rt[5], pz0, Rt[10])));
    float pz = fmaf(Rt[6], px0, fmaf(Rt[7], py0, fmaf(Rt[8], pz0, Rt[11])));
    float lo = fast_atan2f(px, pz);
    float sxz = sqrtf(fmaf(px, px, pz*pz));
    float la = fast_atan2f_pos(py, sxz);
    float gx = fmaf(lo, (float)(W-1)*(0.5f/PI_F), (float)(W-1)*0.5f);
    float gy = fmaf(la, (float)(H-1)*(1.0f/PI_F), (float)(H-1)*0.5f);
    float xf = floorf(gx), yf = floorf(gy);
    ix0 = (int)xf; iy0 = (int)yf;
    ix1 = min(ix0 + 1, W - 1);
    fx = gx - xf; fy = gy - yf;
}

__device__ __forceinline__ void reduce_add(float acc, float inv_count, float* out) {
    #pragma unroll
    for (int o = 16; o > 0; o >>= 1) acc += __shfl_down_sync(0xffffffffu, acc, o);
    __shared__ float sh[8];
    int lane = threadIdx.x & 31, wid = threadIdx.x >> 5;
    if (lane == 0) sh[wid] = acc;
    __syncthreads();
    if (wid == 0) {
        acc = (lane < (int)(blockDim.x >> 5)) ? sh[lane] : 0.0f;
        #pragma unroll
        for (int o = 4; o > 0; o >>= 1) acc += __shfl_down_sync(0xffffffffu, acc, o);
        if (lane == 0) atomicAdd(out, acc * inv_count);
    }
}

// ---------------- unified VP loss body: 4 px/thread ----------------
template <int W, int H>
__device__ __forceinline__ void loss_vp(int vtid,
                        const float* __restrict__ depth, const float* __restrict__ mask,
                        const float* __restrict__ rr,
                        const float4* __restrict__ vpA, const float4* __restrict__ vpB,
                        const float2* __restrict__ lonT, const float2* __restrict__ latT,
                        float inv_count, float* __restrict__ out) {
    constexpr int HW = W * H;
    int pix = vtid * 4;
    int b = pix / HW;
    int p = pix % HW;
    int y = p / W, x = p % W;

    float RtL[24];
    {
        const float4* src = (const float4*)(g_Rt + b*24);
        #pragma unroll
        for (int q = 0; q < 6; q++) {
            float4 v = __ldg(src + q);
            RtL[q*4+0] = v.x; RtL[q*4+1] = v.y; RtL[q*4+2] = v.z; RtL[q*4+3] = v.w;
        }
    }

    float4 d4  = *(const float4*)(depth + pix);
    float2 la2 = __ldg(latT + y);
    float4 m0q = *(const float4*)(mask + ((size_t)(b*NF + 0))*HW + p);
    float4 m1q = *(const float4*)(mask + ((size_t)(b*NF + 1))*HW + p);
    float4 r0q = *(const float4*)(rr + ((size_t)b*CC + 0)*HW + p);
    float4 r1q = *(const float4*)(rr + ((size_t)b*CC + 1)*HW + p);
    float4 r2q = *(const float4*)(rr + ((size_t)b*CC + 2)*HW + p);
    float4 loA = __ldg((const float4*)(lonT + x));      // (sin,cos) x, x+1
    float4 loB = __ldg((const float4*)(lonT + x + 2));  // (sin,cos) x+2, x+3

    float acc = 0.0f;
    #pragma unroll
    for (int k = 0; k < 4; k++) {
        float d = getc(d4, k);
        float2 lo2;
        if (k == 0)      lo2 = make_float2(loA.x, loA.y);
        else if (k == 1) lo2 = make_float2(loA.z, loA.w);
        else if (k == 2) lo2 = make_float2(loB.x, loB.y);
        else             lo2 = make_float2(loB.z, loB.w);
        float px0 = d * (la2.y * lo2.x);
        float py0 = d * la2.x;
        float pz0 = d * (la2.y * lo2.y);
        float r0 = getc(r0q, k), r1 = getc(r1q, k), r2 = getc(r2q, k);
        #pragma unroll
        for (int n = 0; n < NF; n++) {
            int ix0, ix1, iy0; float fx, fy;
            project<W,H>(RtL + n*12, px0, py0, pz0, ix0, ix1, iy0, fx, fy);
            __half2 hwa = __float2half2_rn((1.0f - fx) * (1.0f - fy));
            __half2 hwb = __float2half2_rn((1.0f - fx) * fy);
            __half2 hwc = __float2half2_rn(fx * (1.0f - fy));
            __half2 hwd = __float2half2_rn(fx * fy);
            const float4* base = ((n == 0) ? vpA : vpB) + (size_t)b*HW + (size_t)iy0*W;
            float4 va = __ldg(base + ix0);
            float4 vc = __ldg(base + ix1);
            __half2 vrg = __hmul2(hwa, h2_from_f(va.x));
            __half2 vbp = __hmul2(hwa, h2_from_f(va.y));
            vrg = __hfma2(hwb, h2_from_f(va.z), vrg);  vbp = __hfma2(hwb, h2_from_f(va.w), vbp);
            vrg = __hfma2(hwc, h2_from_f(vc.x), vrg);  vbp = __hfma2(hwc, h2_from_f(vc.y), vbp);
            vrg = __hfma2(hwd, h2_from_f(vc.z), vrg);  vbp = __hfma2(hwd, h2_from_f(vc.w), vbp);
            float2 vf = __half22float2(vrg);
            float vb = __low2float(vbp);
            float m = n ? getc(m1q, k) : getc(m0q, k);
            acc += m * (fabsf(r0 - vf.x) + fabsf(r1 - vf.y) + fabsf(r2 - vb));
        }
    }
    reduce_add(acc, inv_count, out);
}

// ---------------- K4: all loss levels in one grid (4 px/thread) ----------------
// blocks [0,4096): l0; [4096,5120): l1; [5120,5376): l2; [5376,5440): l3
__global__ void loss_all(const float* __restrict__ d0, const float* __restrict__ m0,
                         const float* __restrict__ d1, const float* __restrict__ m1,
                         const float* __restrict__ d2, const float* __restrict__ m2,
                         const float* __restrict__ d3, const float* __restrict__ m3,
                         const float* __restrict__ ref,
                         const float* __restrict__ rr1, const float* __restrict__ rr2,
                         const float* __restrict__ rr3,
                         const float4* __restrict__ vp00, const float4* __restrict__ vp10,
                         const float4* __restrict__ vp01, const float4* __restrict__ vp11,
                         const float4* __restrict__ vp02, const float4* __restrict__ vp12,
                         const float4* __restrict__ vp03, const float4* __restrict__ vp13,
                         const float2* __restrict__ lonT, const float2* __restrict__ latT,
                         float* __restrict__ out) {
    int bx = blockIdx.x;
    if (bx < 4096) {
        loss_vp<1024,512>(bx * 256 + threadIdx.x, d0, m0, ref, vp00, vp10,
                          lonT, latT, 1.0f/(float)(BB*CC*L0), out);
    } else if (bx < 5120) {
        loss_vp<512,256>((bx - 4096) * 256 + threadIdx.x, d1, m1, rr1, vp01, vp11,
                         lonT + 1024, latT + 512, 1.0f/(float)(BB*CC*L1), out);
    } else if (bx < 5376) {
        loss_vp<256,128>((bx - 5120) * 256 + threadIdx.x, d2, m2, rr2, vp02, vp12,
                         lonT + 1536, latT + 768, 1.0f/(float)(BB*CC*L2), out);
    } else {
        loss_vp<128,64>((bx - 5376) * 256 + threadIdx.x, d3, m3, rr3, vp03, vp13,
                        lonT + 1792, latT + 896, 1.0f/(float)(BB*CC*L3), out);
    }
}

static inline int cdiv(int a, int b) { return (a + b - 1) / b; }

extern "C" void kernel_launch(void* const* d_in, const int* in_sizes, int n_in,
                              void* d_out, int out_size) {
    const float* ref   = (const float*)d_in[0];
    const float* dep[4] = {(const float*)d_in[1], (const float*)d_in[3],
                           (const float*)d_in[5], (const float*)d_in[7]};
    const float* msk[4] = {(const float*)d_in[2], (const float*)d_in[4],
                           (const float*)d_in[6], (const float*)d_in[8]};
    const float* tgt0  = (const float*)d_in[9];
    const float* tgt1  = (const float*)d_in[10];
    const float* pose  = (const float*)d_in[11];
    float* out = (float*)d_out;

    float *rr1, *rr2, *rr3;
    float4 *vp00, *vp10, *vp01, *vp11, *vp02, *vp12, *vp03, *vp13;
    float2 *lonT, *latT;
    cudaGetSymbolAddress((void**)&rr1, g_rr1);
    cudaGetSymbolAddress((void**)&rr2, g_rr2);
    cudaGetSymbolAddress((void**)&rr3, g_rr3);
    cudaGetSymbolAddress((void**)&vp00, g_vp0_0);
    cudaGetSymbolAddress((void**)&vp10, g_vp1_0);
    cudaGetSymbolAddress((void**)&vp01, g_vp0_1);
    cudaGetSymbolAddress((void**)&vp11, g_vp1_1);
    cudaGetSymbolAddress((void**)&vp02, g_vp0_2);
    cudaGetSymbolAddress((void**)&vp12, g_vp1_2);
    cudaGetSymbolAddress((void**)&vp03, g_vp0_3);
    cudaGetSymbolAddress((void**)&vp13, g_vp1_3);
    cudaGetSymbolAddress((void**)&lonT, g_lon);
    cudaGetSymbolAddress((void**)&latT, g_lat);

    const int T = 256;

    setup_kernel<<<12, T>>>(pose, out);                                     // 1
    build01<<<16384, T>>>(tgt0, tgt1, ref, vp00, vp10, vp01, vp11, rr1);    // 2
    build23<<<1280, T>>>(vp01, vp11, vp02, vp12, vp03, vp13, rr1, rr2, rr3);// 3
    loss_all<<<5440, T>>>(dep[0], msk[0], dep[1], msk[1], dep[2], msk[2],   // 4 (profiled)
                          dep[3], msk[3], ref, rr1, rr2, rr3,
                          vp00, vp10, vp01, vp11, vp02, vp12, vp03, vp13,
                          lonT, latT, out);
}

// round 16
// speedup vs baseline: 1.0137x; 1.0137x over previous
#include <cuda_runtime.h>
#include <cuda_fp16.h>
#include <math.h>

#define BB 8
#define CC 3
#define NF 2
#define H0 512
#define W0 1024

#define L0 (512*1024)
#define L1 (256*512)
#define L2 (128*256)
#define L3 (64*128)

#define PI_F 3.14159265358979323846f

struct __align__(8) H4 { __half2 rg, bp; };
// VP texel (float4): .x=top rg(half2 bits) .y=top bp .z=bottom rg .w=bottom bp

__device__ __forceinline__ __half2 h2_from_f(float f) {
    __half2 h; *(unsigned*)&h = __float_as_uint(f); return h;
}
__device__ __forceinline__ float f_from_h2(__half2 h) {
    return __uint_as_float(*(unsigned*)&h);
}

// ---- static device scratch ----
__device__ float g_rr1[BB*CC*L1];
__device__ float g_rr2[BB*CC*L2];
__device__ float g_rr3[BB*CC*L3];
__device__ float4 g_vp0[BB*L0];
__device__ float4 g_vp1[BB*L0];
__device__ H4 g_t0_1[BB*L1];
__device__ H4 g_t0_2[BB*L2];
__device__ H4 g_t0_3[BB*L3];
__device__ H4 g_t1_1[BB*L1];
__device__ H4 g_t1_2[BB*L2];
__device__ H4 g_t1_3[BB*L3];
__device__ __align__(16) float g_Rt[BB*NF*12];
__device__ float2 g_lon[1920];
__device__ float2 g_lat[960];

__device__ __forceinline__ H4 pack_h4(float r, float g, float b) {
    H4 o; o.rg = __floats2half2_rn(r, g); o.bp = __floats2half2_rn(b, 0.0f); return o;
}
__device__ __forceinline__ float getc(float4 v, int i) {
    switch (i) { case 0: return v.x; case 1: return v.y; case 2: return v.z; default: return v.w; }
}

// ---------------- setup ----------------
__global__ void setup_kernel(const float* __restrict__ pose, float* __restrict__ out) {
    int idx = blockIdx.x * blockDim.x + threadIdx.x;
    if (idx == 0) out[0] = 0.0f;
    if (idx < BB*NF) {
        const float* p = pose + idx*6;
        float tx = p[0], ty = p[1], tz = p[2];
        float rx = p[3], ry = p[4], rz = p[5];
        float th = sqrtf(rx*rx + ry*ry + rz*rz);
        float inv = 1.0f / fmaxf(th, 1e-8f);
        float kx = rx*inv, ky = ry*inv, kz = rz*inv;
        float s = sinf(th), c = cosf(th), mc = 1.0f - c;
        float* R = g_Rt + idx*12;
        R[0] = 1.0f + mc*(-(ky*ky + kz*kz));
        R[1] = -s*kz + mc*(kx*ky);
        R[2] =  s*ky + mc*(kx*kz);
        R[3] =  s*kz + mc*(kx*ky);
        R[4] = 1.0f + mc*(-(kx*kx + kz*kz));
        R[5] = -s*kx + mc*(ky*kz);
        R[6] = -s*ky + mc*(kx*kz);
        R[7] =  s*kx + mc*(ky*kz);
        R[8] = 1.0f + mc*(-(kx*kx + ky*ky));
        R[9] = tx; R[10] = ty; R[11] = tz;
    }
    if (idx < 1920) {
        int off, w;
        if (idx < 1024)      { off = 0;    w = 1024; }
        else if (idx < 1536) { off = 1024; w = 512;  }
        else if (idx < 1792) { off = 1536; w = 256;  }
        else                 { off = 1792; w = 128;  }
        int x = idx - off;
        float lon = (((float)x + 0.5f) / (float)w * 2.0f - 1.0f) * PI_F;
        g_lon[idx] = make_float2(sinf(lon), cosf(lon));
    } else if (idx < 1920 + 960) {
        int i2 = idx - 1920;
        int off, h;
        if (i2 < 512)      { off = 0;   h = 512; }
        else if (i2 < 768) { off = 512; h = 256; }
        else if (i2 < 896) { off = 768; h = 128; }
        else               { off = 896; h = 64;  }
        int y = i2 - off;
        float lat = -((((float)y + 0.5f) / (float)h) * 2.0f - 1.0f) * (0.5f * PI_F);
        g_lat[i2] = make_float2(sinf(lat), cosf(lat));
    }
}

// ---------------- K2: build level0 VP + level1 H4 targets + ref level1 ----------------
// blocks [0, 4096): tgt path;  blocks [4096, 16384): ref_lvl1 path
__global__ void build01(const float* __restrict__ t0src, const float* __restrict__ t1src,
                        const float* __restrict__ ref,
                        float4* __restrict__ vp0, float4* __restrict__ vp1,
                        H4* __restrict__ d01, H4* __restrict__ d11,
                        float* __restrict__ rr1) {
    int bx = blockIdx.x;
    if (bx < 4096) {
        int z = bx >> 8;
        int b = z >> 1, f = z & 1;
        const float* src = (f ? t1src : t0src) + (size_t)b*CC*L0;
        float4* vp = (f ? vp1 : vp0) + (size_t)b*L0;
        H4* dst1 = (f ? d11 : d01) + (size_t)b*L1;
        int tid = (bx & 255) * 256 + threadIdx.x;  // < 65536
        int tx = tid & 255;
        int ty = tid >> 8;
        int x0 = tx * 4, y0 = ty * 2;
        int y2c = min(y0 + 2, H0 - 1);

        float4 a0 = *(const float4*)(src + (size_t)0*L0 + (size_t)y0*W0 + x0);
        float4 b0 = *(const float4*)(src + (size_t)1*L0 + (size_t)y0*W0 + x0);
        float4 c0 = *(const float4*)(src + (size_t)2*L0 + (size_t)y0*W0 + x0);
        float4 a1 = *(const float4*)(src + (size_t)0*L0 + (size_t)(y0+1)*W0 + x0);
        float4 b1 = *(const float4*)(src + (size_t)1*L0 + (size_t)(y0+1)*W0 + x0);
        float4 c1 = *(const float4*)(src + (size_t)2*L0 + (size_t)(y0+1)*W0 + x0);
        float4 a2 = *(const float4*)(src + (size_t)0*L0 + (size_t)y2c*W0 + x0);
        float4 b2 = *(const float4*)(src + (size_t)1*L0 + (size_t)y2c*W0 + x0);
        float4 c2 = *(const float4*)(src + (size_t)2*L0 + (size_t)y2c*W0 + x0);

        float4* r0 = vp + (size_t)y0*W0 + x0;
        float4* r1 = vp + (size_t)(y0+1)*W0 + x0;
        #pragma unroll
        for (int i = 0; i < 4; i++) {
            float trg = f_from_h2(__floats2half2_rn(getc(a0,i), getc(b0,i)));
            float tbp = f_from_h2(__floats2half2_rn(getc(c0,i), 0.0f));
            float mrg = f_from_h2(__floats2half2_rn(getc(a1,i), getc(b1,i)));
            float mbp = f_from_h2(__floats2half2_rn(getc(c1,i), 0.0f));
            float brg = f_from_h2(__floats2half2_rn(getc(a2,i), getc(b2,i)));
            float bbp = f_from_h2(__floats2half2_rn(getc(c2,i), 0.0f));
            r0[i] = make_float4(trg, tbp, mrg, mbp);
            r1[i] = make_float4(mrg, mbp, brg, bbp);
        }

        H4* p1 = dst1 + (size_t)ty*(W0/2) + tx*2;
        p1[0] = pack_h4(0.25f*(a0.x + a0.y + a1.x + a1.y),
                        0.25f*(b0.x + b0.y + b1.x + b1.y),
                        0.25f*(c0.x + c0.y + c1.x + c1.y));
        p1[1] = pack_h4(0.25f*(a0.z + a0.w + a1.z + a1.w),
                        0.25f*(b0.z + b0.w + b1.z + b1.w),
                        0.25f*(c0.z + c0.w + c1.z + c1.w));
    } else {
        int idx = (bx - 4096) * 256 + threadIdx.x;   // < BB*CC*L1
        const int w2 = 512, w = 1024;
        int img = idx / L1, p = idx % L1;
        int y = p / w2, x = p % w2;
        const float* s = ref + ((size_t)img*512 + y*2) * w + x*2;
        rr1[idx] = 0.25f*(s[0] + s[1] + s[w] + s[w+1]);
    }
}

__device__ __forceinline__ float3 h4_to_f3(H4 v) {
    float2 rg = __half22float2(v.rg);
    float2 bp = __half22float2(v.bp);
    return make_float3(rg.x, rg.y, bp.x);
}

// ---------------- K3: target levels 2+3 and ref levels 2+3 ----------------
// blocks [0,512): tgt path (f = bx>>8);  blocks [512, 1280): ref path
__global__ void build23(const H4* __restrict__ s0, const H4* __restrict__ s1,
                        H4* __restrict__ d20, H4* __restrict__ d21,
                        H4* __restrict__ d30, H4* __restrict__ d31,
                        const float* __restrict__ rr1, float* __restrict__ rr2,
                        float* __restrict__ rr3) {
    int bx = blockIdx.x;
    if (bx < 512) {
        int f = bx >> 8;
        int idx = (bx & 255) * 256 + threadIdx.x;     // < BB*L3
        const H4* l1 = (f ? s1 : s0);
        H4* l2 = (f ? d21 : d20);
        H4* l3 = (f ? d31 : d30);
        const int w3 = 128, w2 = 256, w1 = 512;
        int b = idx / L3, p = idx % L3;
        int x3 = p % w3, y3 = p / w3;
        const H4* base1 = l1 + (size_t)b*L1 + (size_t)(y3*4)*w1 + x3*4;
        H4* base2 = l2 + (size_t)b*L2 + (size_t)(y3*2)*w2 + x3*2;

        float3 acc3 = make_float3(0.f, 0.f, 0.f);
        #pragma unroll
        for (int dy = 0; dy < 2; dy++) {
            #pragma unroll
            for (int dx = 0; dx < 2; dx++) {
                float3 s = make_float3(0.f, 0.f, 0.f);
                #pragma unroll
                for (int iy = 0; iy < 2; iy++) {
                    #pragma unroll
                    for (int ix = 0; ix < 2; ix++) {
                        float3 v = h4_to_f3(base1[(size_t)(dy*2+iy)*w1 + dx*2+ix]);
                        s.x += v.x; s.y += v.y; s.z += v.z;
                    }
                }
                s.x *= 0.25f; s.y *= 0.25f; s.z *= 0.25f;
                base2[(size_t)dy*w2 + dx] = pack_h4(s.x, s.y, s.z);
                acc3.x += s.x; acc3.y += s.y; acc3.z += s.z;
            }
        }
        l3[(size_t)b*L3 + p] = pack_h4(0.25f*acc3.x, 0.25f*acc3.y, 0.25f*acc3.z);
    } else {
        int idx = (bx - 512) * 256 + threadIdx.x;     // < BB*CC*L3
        const int w3 = 128, w2 = 256, w1 = 512;
        int img = idx / L3, p = idx % L3;
        int x3 = p % w3, y3 = p / w3;
        const float* base1 = rr1 + (size_t)img*L1 + (size_t)(y3*4)*w1 + x3*4;
        float* base2 = rr2 + (size_t)img*L2 + (size_t)(y3*2)*w2 + x3*2;
        float acc = 0.0f;
        #pragma unroll
        for (int dy = 0; dy < 2; dy++) {
            #pragma unroll
            for (int dx = 0; dx < 2; dx++) {
                const float* s = base1 + (size_t)(dy*2)*w1 + dx*2;
                float v = 0.25f*(s[0] + s[1] + s[w1] + s[w1+1]);
                base2[(size_t)dy*w2 + dx] = v;
                acc += v;
            }
        }
        rr3[(size_t)img*L3 + p] = 0.25f*acc;
    }
}

// ---------------- fast atan2, single MUFU divide ----------------
__device__ __forceinline__ float atan_poly(float x) {
    float z = x * x;
    float r = fmaf(8.05374449538e-2f, z, -1.38776856032e-1f);
    r = fmaf(r, z, 1.99777106478e-1f);
    r = fmaf(r, z, -3.33329491539e-1f);
    return fmaf(r * z, x, x);
}
__device__ __forceinline__ float fast_atan2f(float y, float x) {
    float ay = fabsf(y), ax = fabsf(x);
    float mx = fmaxf(ax, ay), mn = fminf(ax, ay);
    bool big = mn > 0.41421356f * mx;
    float num = big ? (mn - mx) : mn;
    float den = big ? (mn + mx) : mx;
    float arg = __fdividef(num, den);
    float r = atan_poly(arg) + (big ? 0.78539816339744831f : 0.0f);
    if (ay > ax) r = 1.57079632679489662f - r;
    if (x < 0.0f) r = PI_F - r;
    return copysignf(r, y);
}
__device__ __forceinline__ float fast_atan2f_pos(float y, float x) {
    float ay = fabsf(y);
    float mx = fmaxf(x, ay), mn = fminf(x, ay);
    bool big = mn > 0.41421356f * mx;
    float num = big ? (mn - mx) : mn;
    float den = big ? (mn + mx) : mx;
    float arg = __fdividef(num, den);
    float r = atan_poly(arg) + (big ? 0.78539816339744831f : 0.0f);
    if (ay > x) r = 1.57079632679489662f - r;
    return copysignf(r, y);
}

template <int W, int H>
__device__ __forceinline__ void project(const float* Rt, float px0, float py0, float pz0,
                                        int& ix0, int& ix1, int& iy0,
                                        float& fx, float& fy) {
    float px = fmaf(Rt[0], px0, fmaf(Rt[1], py0, fmaf(Rt[2], pz0, Rt[9])));
    float py = fmaf(Rt[3], px0, fmaf(Rt[4], py0, fmaf(Rt[5], pz0, Rt[10])));
    float pz = fmaf(Rt[6], px0, fmaf(Rt[7], py0, fmaf(Rt[8], pz0, Rt[11])));
    float lo = fast_atan2f(px, pz);
    float sxz = sqrtf(fmaf(px, px, pz*pz));
    float la = fast_atan2f_pos(py, sxz);
    float gx = fmaf(lo, (float)(W-1)*(0.5f/PI_F), (float)(W-1)*0.5f);
    float gy = fmaf(la, (float)(H-1)*(1.0f/PI_F), (float)(H-1)*0.5f);
    float xf = floorf(gx), yf = floorf(gy);
    ix0 = (int)xf; iy0 = (int)yf;
    ix1 = min(ix0 + 1, W - 1);
    fx = gx - xf; fy = gy - yf;
}

__device__ __forceinline__ void reduce_add(float acc, float inv_count, float* out) {
    #pragma unroll
    for (int o = 16; o > 0; o >>= 1) acc += __shfl_down_sync(0xffffffffu, acc, o);
    __shared__ float sh[8];
    int lane = threadIdx.x & 31, wid = threadIdx.x >> 5;
    if (lane == 0) sh[wid] = acc;
    __syncthreads();
    if (wid == 0) {
        acc = (lane < (int)(blockDim.x >> 5)) ? sh[lane] : 0.0f;
        #pragma unroll
        for (int o = 4; o > 0; o >>= 1) acc += __shfl_down_sync(0xffffffffu, acc, o);
        if (lane == 0) atomicAdd(out, acc * inv_count);
    }
}

// ---------------- loss level0: VP taps, 4 px/thread ----------------
__device__ __forceinline__ void loss_l0_body(int vtid,
                        const float* __restrict__ depth, const float* __restrict__ mask,
                        const float* __restrict__ rr,
                        const float4* __restrict__ vpA, const float4* __restrict__ vpB,
                        const float2* __restrict__ lonT, const float2* __restrict__ latT,
                        float* __restrict__ out) {
    constexpr int W = 1024, H = 512, HW = W*H;
    const float inv_count = 1.0f/(float)(BB*CC*L0);
    int pix = vtid * 4;
    int b = pix / HW;
    int p = pix % HW;
    int y = p / W, x = p % W;

    float RtL[24];
    {
        const float4* src = (const float4*)(g_Rt + b*24);
        #pragma unroll
        for (int q = 0; q < 6; q++) {
            float4 v = __ldg(src + q);
            RtL[q*4+0] = v.x; RtL[q*4+1] = v.y; RtL[q*4+2] = v.z; RtL[q*4+3] = v.w;
        }
    }

    float4 d4  = *(const float4*)(depth + pix);
    float2 la2 = __ldg(latT + y);
    float4 m0q = *(const float4*)(mask + ((size_t)(b*NF + 0))*HW + p);
    float4 m1q = *(const float4*)(mask + ((size_t)(b*NF + 1))*HW + p);
    float4 r0q = *(const float4*)(rr + ((size_t)b*CC + 0)*HW + p);
    float4 r1q = *(const float4*)(rr + ((size_t)b*CC + 1)*HW + p);
    float4 r2q = *(const float4*)(rr + ((size_t)b*CC + 2)*HW + p);
    float4 loA = __ldg((const float4*)(lonT + x));
    float4 loB = __ldg((const float4*)(lonT + x + 2));

    float acc = 0.0f;
    #pragma unroll
    for (int k = 0; k < 4; k++) {
        float d = getc(d4, k);
        float2 lo2;
        if (k == 0)      lo2 = make_float2(loA.x, loA.y);
        else if (k == 1) lo2 = make_float2(loA.z, loA.w);
        else if (k == 2) lo2 = make_float2(loB.x, loB.y);
        else             lo2 = make_float2(loB.z, loB.w);
        float px0 = d * (la2.y * lo2.x);
        float py0 = d * la2.x;
        float pz0 = d * (la2.y * lo2.y);
        float r0 = getc(r0q, k), r1 = getc(r1q, k), r2 = getc(r2q, k);
        #pragma unroll
        for (int n = 0; n < NF; n++) {
            int ix0, ix1, iy0; float fx, fy;
            project<W,H>(RtL + n*12, px0, py0, pz0, ix0, ix1, iy0, fx, fy);
            __half2 hwa = __float2half2_rn((1.0f - fx) * (1.0f - fy));
            __half2 hwb = __float2half2_rn((1.0f - fx) * fy);
            __half2 hwc = __float2half2_rn(fx * (1.0f - fy));
            __half2 hwd = __float2half2_rn(fx * fy);
            const float4* base = ((n == 0) ? vpA : vpB) + (size_t)b*HW + (size_t)iy0*W;
            float4 va = __ldg(base + ix0);
            float4 vc = __ldg(base + ix1);
            __half2 vrg = __hmul2(hwa, h2_from_f(va.x));
            __half2 vbp = __hmul2(hwa, h2_from_f(va.y));
            vrg = __hfma2(hwb, h2_from_f(va.z), vrg);  vbp = __hfma2(hwb, h2_from_f(va.w), vbp);
            vrg = __hfma2(hwc, h2_from_f(vc.x), vrg);  vbp = __hfma2(hwc, h2_from_f(vc.y), vbp);
            vrg = __hfma2(hwd, h2_from_f(vc.z), vrg);  vbp = __hfma2(hwd, h2_from_f(vc.w), vbp);
            float2 vf = __half22float2(vrg);
            float vb = __low2float(vbp);
            float m = n ? getc(m1q, k) : getc(m0q, k);
            acc += m * (fabsf(r0 - vf.x) + fabsf(r1 - vf.y) + fabsf(r2 - vb));
        }
    }
    reduce_add(acc, inv_count, out);
}

// ---------------- loss small levels: H4 taps, 4 px/thread ----------------
template <int W, int H>
__device__ __forceinline__ void loss_body(int vtid,
                                          const float* __restrict__ depth,
                                          const float* __restrict__ mask,
                                          const float* __restrict__ rr,
                                          const H4* __restrict__ tgA,
                                          const H4* __restrict__ tgB,
                                          const float2* __restrict__ lonT,
                                          const float2* __restrict__ latT,
                                          float inv_count,
                                          float* __restrict__ out) {
    constexpr int HW = W * H;
    int pix = vtid * 4;
    int b = pix / HW;
    int p = pix % HW;
    int y = p / W, x = p % W;

    float RtL[24];
    {
        const float4* src = (const float4*)(g_Rt + b*24);
        #pragma unroll
        for (int q = 0; q < 6; q++) {
            float4 v = __ldg(src + q);
            RtL[q*4+0] = v.x; RtL[q*4+1] = v.y; RtL[q*4+2] = v.z; RtL[q*4+3] = v.w;
        }
    }

    float4 d4  = *(const float4*)(depth + pix);
    float2 la2 = __ldg(latT + y);
    float4 m0q = *(const float4*)(mask + ((size_t)(b*NF + 0))*HW + p);
    float4 m1q = *(const float4*)(mask + ((size_t)(b*NF + 1))*HW + p);
    float4 r0q = *(const float4*)(rr + ((size_t)b*CC + 0)*HW + p);
    float4 r1q = *(const float4*)(rr + ((size_t)b*CC + 1)*HW + p);
    float4 r2q = *(const float4*)(rr + ((size_t)b*CC + 2)*HW + p);
    float4 loA = __ldg((const float4*)(lonT + x));
    float4 loB = __ldg((const float4*)(lonT + x + 2));

    float acc = 0.0f;
    #pragma unroll
    for (int k = 0; k < 4; k++) {
        float d = getc(d4, k);
        float2 lo2;
        if (k == 0)      lo2 = make_float2(loA.x, loA.y);
        else if (k == 1) lo2 = make_float2(loA.z, loA.w);
        else if (k == 2) lo2 = make_float2(loB.x, loB.y);
        else             lo2 = make_float2(loB.z, loB.w);
        float px0 = d * (la2.y * lo2.x);
        float py0 = d * la2.x;
        float pz0 = d * (la2.y * lo2.y);
        float r0 = getc(r0q, k), r1 = getc(r1q, k), r2 = getc(r2q, k);
        #pragma unroll
        for (int n = 0; n < NF; n++) {
            int ix0, ix1, iy0; float fx, fy;
            project<W,H>(RtL + n*12, px0, py0, pz0, ix0, ix1, iy0, fx, fy);
            int iy1 = min(iy0 + 1, H - 1);
            __half2 hwa = __float2half2_rn((1.0f - fx) * (1.0f - fy));
            __half2 hwb = __float2half2_rn((1.0f - fx) * fy);
            __half2 hwc = __float2half2_rn(fx * (1.0f - fy));
            __half2 hwd = __float2half2_rn(fx * fy);
            const H4* base = ((n == 0) ? tgA : tgB) + (size_t)b*HW;
            const H4* row0 = base + (size_t)iy0*W;
            const H4* row1 = base + (size_t)iy1*W;
            H4 ta = row0[ix0];
            H4 tb = row1[ix0];
            H4 tc = row0[ix1];
            H4 td = row1[ix1];
            __half2 vrg = __hmul2(hwa, ta.rg);
            __half2 vbp = __hmul2(hwa, ta.bp);
            vrg = __hfma2(hwb, tb.rg, vrg);  vbp = __hfma2(hwb, tb.bp, vbp);
            vrg = __hfma2(hwc, tc.rg, vrg);  vbp = __hfma2(hwc, tc.bp, vbp);
            vrg = __hfma2(hwd, td.rg, vrg);  vbp = __hfma2(hwd, td.bp, vbp);
            float2 vf = __half22float2(vrg);
            float vb = __low2float(vbp);
            float m = n ? getc(m1q, k) : getc(m0q, k);
            acc += m * (fabsf(r0 - vf.x) + fabsf(r1 - vf.y) + fabsf(r2 - vb));
        }
    }
    reduce_add(acc, inv_count, out);
}

// ---------------- K4: all loss levels in one grid (4 px/thread) ----------------
// blocks [0,4096): l0; [4096,5120): l1; [5120,5376): l2; [5376,5440): l3
__global__ void loss_all(const float* __restrict__ d0, const float* __restrict__ m0,
                         const float* __restrict__ d1, const float* __restrict__ m1,
                         const float* __restrict__ d2, const float* __restrict__ m2,
                         const float* __restrict__ d3, const float* __restrict__ m3,
                         const float* __restrict__ ref,
                         const float* __restrict__ rr1, const float* __restrict__ rr2,
                         const float* __restrict__ rr3,
                         const float4* __restrict__ vp0, const float4* __restrict__ vp1,
                         const H4* __restrict__ t01, const H4* __restrict__ t11,
                         const H4* __restrict__ t02, const H4* __restrict__ t12,
                         const H4* __restrict__ t03, const H4* __restrict__ t13,
                         const float2* __restrict__ lonT, const float2* __restrict__ latT,
                         float* __restrict__ out) {
    int bx = blockIdx.x;
    if (bx < 4096) {
        loss_l0_body(bx * 256 + threadIdx.x, d0, m0, ref, vp0, vp1, lonT, latT, out);
    } else if (bx < 5120) {
        loss_body<512,256>((bx - 4096) * 256 + threadIdx.x, d1, m1, rr1, t01, t11,
                           lonT + 1024, latT + 512, 1.0f/(float)(BB*CC*L1), out);
    } else if (bx < 5376) {
        loss_body<256,128>((bx - 5120) * 256 + threadIdx.x, d2, m2, rr2, t02, t12,
                           lonT + 1536, latT + 768, 1.0f/(float)(BB*CC*L2), out);
    } else {
        loss_body<128,64>((bx - 5376) * 256 + threadIdx.x, d3, m3, rr3, t03, t13,
                          lonT + 1792, latT + 896, 1.0f/(float)(BB*CC*L3), out);
    }
}

static inline int cdiv(int a, int b) { return (a + b - 1) / b; }

extern "C" void kernel_launch(void* const* d_in, const int* in_sizes, int n_in,
                              void* d_out, int out_size) {
    const float* ref   = (const float*)d_in[0];
    const float* dep[4] = {(const float*)d_in[1], (const float*)d_in[3],
                           (const float*)d_in[5], (const float*)d_in[7]};
    const float* msk[4] = {(const float*)d_in[2], (const float*)d_in[4],
                           (const float*)d_in[6], (const float*)d_in[8]};
    const float* tgt0  = (const float*)d_in[9];
    const float* tgt1  = (const float*)d_in[10];
    const float* pose  = (const float*)d_in[11];
    float* out = (float*)d_out;

    float *rr1, *rr2, *rr3;
    float4 *vp0, *vp1;
    H4 *t01, *t02, *t03, *t11, *t12, *t13;
    float2 *lonT, *latT;
    cudaGetSymbolAddress((void**)&rr1, g_rr1);
    cudaGetSymbolAddress((void**)&rr2, g_rr2);
    cudaGetSymbolAddress((void**)&rr3, g_rr3);
    cudaGetSymbolAddress((void**)&vp0, g_vp0);
    cudaGetSymbolAddress((void**)&vp1, g_vp1);
    cudaGetSymbolAddress((void**)&t01, g_t0_1);
    cudaGetSymbolAddress((void**)&t02, g_t0_2);
    cudaGetSymbolAddress((void**)&t03, g_t0_3);
    cudaGetSymbolAddress((void**)&t11, g_t1_1);
    cudaGetSymbolAddress((void**)&t12, g_t1_2);
    cudaGetSymbolAddress((void**)&t13, g_t1_3);
    cudaGetSymbolAddress((void**)&lonT, g_lon);
    cudaGetSymbolAddress((void**)&latT, g_lat);

    const int T = 256;

    setup_kernel<<<12, T>>>(pose, out);                                    // 1
    build01<<<16384, T>>>(tgt0, tgt1, ref, vp0, vp1, t01, t11, rr1);       // 2
    build23<<<1280, T>>>(t01, t11, t02, t12, t03, t13, rr1, rr2, rr3);     // 3
    loss_all<<<5440, T>>>(dep[0], msk[0], dep[1], msk[1], dep[2], msk[2],  // 4 (profiled)
                          dep[3], msk[3], ref, rr1, rr2, rr3, vp0, vp1,
                          t01, t11, t02, t12, t03, t13, lonT, latT, out);
}

// round 17
// speedup vs baseline: 1.1910x; 1.1749x over previous
#include <cuda_runtime.h>
#include <cuda_fp16.h>
#include <math.h>

#define BB 8
#define CC 3
#define NF 2
#define H0 512
#define W0 1024

#define L0 (512*1024)
#define L1 (256*512)
#define L2 (128*256)
#define L3 (64*128)

#define PI_F 3.14159265358979323846f

struct __align__(8) H4 { __half2 rg, bp; };
// u8 VP texel (uint2): .x = top r|g<<8|b<<16, .y = bottom r|g<<8|b<<16 (bottom = row y+1 clamped)

__device__ __forceinline__ __half2 h2_from_u(unsigned u) {
    __half2 h; *(unsigned*)&h = u; return h;
}
__device__ __forceinline__ float f_from_h2(__half2 h) {
    return __uint_as_float(*(unsigned*)&h);
}

// ---- static device scratch ----
__device__ float g_rr1[BB*CC*L1];
__device__ float g_rr2[BB*CC*L2];
__device__ float g_rr3[BB*CC*L3];
__device__ uint2 g_vp0[BB*L0];
__device__ uint2 g_vp1[BB*L0];
__device__ H4 g_t0_1[BB*L1];
__device__ H4 g_t0_2[BB*L2];
__device__ H4 g_t0_3[BB*L3];
__device__ H4 g_t1_1[BB*L1];
__device__ H4 g_t1_2[BB*L2];
__device__ H4 g_t1_3[BB*L3];
__device__ __align__(16) float g_Rt[BB*NF*12];
__device__ float2 g_lon[1920];
__device__ float2 g_lat[960];

__device__ __forceinline__ H4 pack_h4(float r, float g, float b) {
    H4 o; o.rg = __floats2half2_rn(r, g); o.bp = __floats2half2_rn(b, 0.0f); return o;
}
__device__ __forceinline__ float getc(float4 v, int i) {
    switch (i) { case 0: return v.x; case 1: return v.y; case 2: return v.z; default: return v.w; }
}
__device__ __forceinline__ unsigned pack_rgb8(float r, float g, float b) {
    unsigned ri = (unsigned)__fmaf_rn(__saturatef(r), 255.0f, 0.5f);
    unsigned gi = (unsigned)__fmaf_rn(__saturatef(g), 255.0f, 0.5f);
    unsigned bi = (unsigned)__fmaf_rn(__saturatef(b), 255.0f, 0.5f);
    return ri | (gi << 8) | (bi << 16);
}

// ---------------- setup ----------------
__global__ void setup_kernel(const float* __restrict__ pose, float* __restrict__ out) {
    int idx = blockIdx.x * blockDim.x + threadIdx.x;
    if (idx == 0) out[0] = 0.0f;
    if (idx < BB*NF) {
        const float* p = pose + idx*6;
        float tx = p[0], ty = p[1], tz = p[2];
        float rx = p[3], ry = p[4], rz = p[5];
        float th = sqrtf(rx*rx + ry*ry + rz*rz);
        float inv = 1.0f / fmaxf(th, 1e-8f);
        float kx = rx*inv, ky = ry*inv, kz = rz*inv;
        float s = sinf(th), c = cosf(th), mc = 1.0f - c;
        float* R = g_Rt + idx*12;
        R[0] = 1.0f + mc*(-(ky*ky + kz*kz));
        R[1] = -s*kz + mc*(kx*ky);
        R[2] =  s*ky + mc*(kx*kz);
        R[3] =  s*kz + mc*(kx*ky);
        R[4] = 1.0f + mc*(-(kx*kx + kz*kz));
        R[5] = -s*kx + mc*(ky*kz);
        R[6] = -s*ky + mc*(kx*kz);
        R[7] =  s*kx + mc*(ky*kz);
        R[8] = 1.0f + mc*(-(kx*kx + ky*ky));
        R[9] = tx; R[10] = ty; R[11] = tz;
    }
    if (idx < 1920) {
        int off, w;
        if (idx < 1024)      { off = 0;    w = 1024; }
        else if (idx < 1536) { off = 1024; w = 512;  }
        else if (idx < 1792) { off = 1536; w = 256;  }
        else                 { off = 1792; w = 128;  }
        int x = idx - off;
        float lon = (((float)x + 0.5f) / (float)w * 2.0f - 1.0f) * PI_F;
        g_lon[idx] = make_float2(sinf(lon), cosf(lon));
    } else if (idx < 1920 + 960) {
        int i2 = idx - 1920;
        int off, h;
        if (i2 < 512)      { off = 0;   h = 512; }
        else if (i2 < 768) { off = 512; h = 256; }
        else if (i2 < 896) { off = 768; h = 128; }
        else               { off = 896; h = 64;  }
        int y = i2 - off;
        float lat = -((((float)y + 0.5f) / (float)h) * 2.0f - 1.0f) * (0.5f * PI_F);
        g_lat[i2] = make_float2(sinf(lat), cosf(lat));
    }
}

// ---------------- K2: build level0 u8-VP + level1 H4 targets + ref level1 ----------------
// blocks [0, 4096): tgt path;  blocks [4096, 16384): ref_lvl1 path
__global__ void build01(const float* __restrict__ t0src, const float* __restrict__ t1src,
                        const float* __restrict__ ref,
                        uint2* __restrict__ vp0, uint2* __restrict__ vp1,
                        H4* __restrict__ d01, H4* __restrict__ d11,
                        float* __restrict__ rr1) {
    int bx = blockIdx.x;
    if (bx < 4096) {
        int z = bx >> 8;
        int b = z >> 1, f = z & 1;
        const float* src = (f ? t1src : t0src) + (size_t)b*CC*L0;
        uint2* vp = (f ? vp1 : vp0) + (size_t)b*L0;
        H4* dst1 = (f ? d11 : d01) + (size_t)b*L1;
        int tid = (bx & 255) * 256 + threadIdx.x;  // < 65536
        int tx = tid & 255;
        int ty = tid >> 8;
        int x0 = tx * 4, y0 = ty * 2;
        int y2c = min(y0 + 2, H0 - 1);

        float4 a0 = *(const float4*)(src + (size_t)0*L0 + (size_t)y0*W0 + x0);
        float4 b0 = *(const float4*)(src + (size_t)1*L0 + (size_t)y0*W0 + x0);
        float4 c0 = *(const float4*)(src + (size_t)2*L0 + (size_t)y0*W0 + x0);
        float4 a1 = *(const float4*)(src + (size_t)0*L0 + (size_t)(y0+1)*W0 + x0);
        float4 b1 = *(const float4*)(src + (size_t)1*L0 + (size_t)(y0+1)*W0 + x0);
        float4 c1 = *(const float4*)(src + (size_t)2*L0 + (size_t)(y0+1)*W0 + x0);
        float4 a2 = *(const float4*)(src + (size_t)0*L0 + (size_t)y2c*W0 + x0);
        float4 b2 = *(const float4*)(src + (size_t)1*L0 + (size_t)y2c*W0 + x0);
        float4 c2 = *(const float4*)(src + (size_t)2*L0 + (size_t)y2c*W0 + x0);

        uint2* r0 = vp + (size_t)y0*W0 + x0;
        uint2* r1 = vp + (size_t)(y0+1)*W0 + x0;
        #pragma unroll
        for (int i = 0; i < 4; i++) {
            unsigned top = pack_rgb8(getc(a0,i), getc(b0,i), getc(c0,i));
            unsigned mid = pack_rgb8(getc(a1,i), getc(b1,i), getc(c1,i));
            unsigned bot = pack_rgb8(getc(a2,i), getc(b2,i), getc(c2,i));
            r0[i] = make_uint2(top, mid);
            r1[i] = make_uint2(mid, bot);
        }

        H4* p1 = dst1 + (size_t)ty*(W0/2) + tx*2;
        p1[0] = pack_h4(0.25f*(a0.x + a0.y + a1.x + a1.y),
                        0.25f*(b0.x + b0.y + b1.x + b1.y),
                        0.25f*(c0.x + c0.y + c1.x + c1.y));
        p1[1] = pack_h4(0.25f*(a0.z + a0.w + a1.z + a1.w),
                        0.25f*(b0.z + b0.w + b1.z + b1.w),
                        0.25f*(c0.z + c0.w + c1.z + c1.w));
    } else {
        int idx = (bx - 4096) * 256 + threadIdx.x;   // < BB*CC*L1
        const int w2 = 512, w = 1024;
        int img = idx / L1, p = idx % L1;
        int y = p / w2, x = p % w2;
        const float* s = ref + ((size_t)img*512 + y*2) * w + x*2;
        rr1[idx] = 0.25f*(s[0] + s[1] + s[w] + s[w+1]);
    }
}

__device__ __forceinline__ float3 h4_to_f3(H4 v) {
    float2 rg = __half22float2(v.rg);
    float2 bp = __half22float2(v.bp);
    return make_float3(rg.x, rg.y, bp.x);
}

// ---------------- K3: target levels 2+3 and ref levels 2+3 ----------------
__global__ void build23(const H4* __restrict__ s0, const H4* __restrict__ s1,
                        H4* __restrict__ d20, H4* __restrict__ d21,
                        H4* __restrict__ d30, H4* __restrict__ d31,
                        const float* __restrict__ rr1, float* __restrict__ rr2,
                        float* __restrict__ rr3) {
    int bx = blockIdx.x;
    if (bx < 512) {
        int f = bx >> 8;
        int idx = (bx & 255) * 256 + threadIdx.x;     // < BB*L3
        const H4* l1 = (f ? s1 : s0);
        H4* l2 = (f ? d21 : d20);
        H4* l3 = (f ? d31 : d30);
        const int w3 = 128, w2 = 256, w1 = 512;
        int b = idx / L3, p = idx % L3;
        int x3 = p % w3, y3 = p / w3;
        const H4* base1 = l1 + (size_t)b*L1 + (size_t)(y3*4)*w1 + x3*4;
        H4* base2 = l2 + (size_t)b*L2 + (size_t)(y3*2)*w2 + x3*2;

        float3 acc3 = make_float3(0.f, 0.f, 0.f);
        #pragma unroll
        for (int dy = 0; dy < 2; dy++) {
            #pragma unroll
            for (int dx = 0; dx < 2; dx++) {
                float3 s = make_float3(0.f, 0.f, 0.f);
                #pragma unroll
                for (int iy = 0; iy < 2; iy++) {
                    #pragma unroll
                    for (int ix = 0; ix < 2; ix++) {
                        float3 v = h4_to_f3(base1[(size_t)(dy*2+iy)*w1 + dx*2+ix]);
                        s.x += v.x; s.y += v.y; s.z += v.z;
                    }
                }
                s.x *= 0.25f; s.y *= 0.25f; s.z *= 0.25f;
                base2[(size_t)dy*w2 + dx] = pack_h4(s.x, s.y, s.z);
                acc3.x += s.x; acc3.y += s.y; acc3.z += s.z;
            }
        }
        l3[(size_t)b*L3 + p] = pack_h4(0.25f*acc3.x, 0.25f*acc3.y, 0.25f*acc3.z);
    } else {
        int idx = (bx - 512) * 256 + threadIdx.x;     // < BB*CC*L3
        const int w3 = 128, w2 = 256, w1 = 512;
        int img = idx / L3, p = idx % L3;
        int x3 = p % w3, y3 = p / w3;
        const float* base1 = rr1 + (size_t)img*L1 + (size_t)(y3*4)*w1 + x3*4;
        float* base2 = rr2 + (size_t)img*L2 + (size_t)(y3*2)*w2 + x3*2;
        float acc = 0.0f;
        #pragma unroll
        for (int dy = 0; dy < 2; dy++) {
            #pragma unroll
            for (int dx = 0; dx < 2; dx++) {
                const float* s = base1 + (size_t)(dy*2)*w1 + dx*2;
                float v = 0.25f*(s[0] + s[1] + s[w1] + s[w1+1]);
                base2[(size_t)dy*w2 + dx] = v;
                acc += v;
            }
        }
        rr3[(size_t)img*L3 + p] = 0.25f*acc;
    }
}

// ---------------- fast atan2, single MUFU divide ----------------
__device__ __forceinline__ float atan_poly(float x) {
    float z = x * x;
    float r = fmaf(8.05374449538e-2f, z, -1.38776856032e-1f);
    r = fmaf(r, z, 1.99777106478e-1f);
    r = fmaf(r, z, -3.33329491539e-1f);
    return fmaf(r * z, x, x);
}
__device__ __forceinline__ float fast_atan2f(float y, float x) {
    float ay = fabsf(y), ax = fabsf(x);
    float mx = fmaxf(ax, ay), mn = fminf(ax, ay);
    bool big = mn > 0.41421356f * mx;
    float num = big ? (mn - mx) : mn;
    float den = big ? (mn + mx) : mx;
    float arg = __fdividef(num, den);
    float r = atan_poly(arg) + (big ? 0.78539816339744831f : 0.0f);
    if (ay > ax) r = 1.57079632679489662f - r;
    if (x < 0.0f) r = PI_F - r;
    return copysignf(r, y);
}
__device__ __forceinline__ float fast_atan2f_pos(float y, float x) {
    float ay = fabsf(y);
    float mx = fmaxf(x, ay), mn = fminf(x, ay);
    bool big = mn > 0.41421356f * mx;
    float num = big ? (mn - mx) : mn;
    float den = big ? (mn + mx) : mx;
    float arg = __fdividef(num, den);
    float r = atan_poly(arg) + (big ? 0.78539816339744831f : 0.0f);
    if (ay > x) r = 1.57079632679489662f - r;
    return copysignf(r, y);
}

template <int W, int H>
__device__ __forceinline__ void project(const float* Rt, float px0, float py0, float pz0,
                                        int& ix0, int& ix1, int& iy0,
                                        float& fx, float& fy) {
    float px = fmaf(Rt[0], px0, fmaf(Rt[1], py0, fmaf(Rt[2], pz0, Rt[9])));
    float py = fmaf(Rt[3], px0, fmaf(Rt[4], py0, fmaf(Rt[5], pz0, Rt[10])));
    float pz = fmaf(Rt[6], px0, fmaf(Rt[7], py0, fmaf(Rt[8], pz0, Rt[11])));
    float lo = fast_atan2f(px, pz);
    float sxz = sqrtf(fmaf(px, px, pz*pz));
    float la = fast_atan2f_pos(py, sxz);
    float gx = fmaf(lo, (float)(W-1)*(0.5f/PI_F), (float)(W-1)*0.5f);
    float gy = fmaf(la, (float)(H-1)*(1.0f/PI_F), (float)(H-1)*0.5f);
    float xf = floorf(gx), yf = floorf(gy);
    ix0 = (int)xf; iy0 = (int)yf;
    ix1 = min(ix0 + 1, W - 1);
    fx = gx - xf; fy = gy - yf;
}

__device__ __forceinline__ void reduce_add(float acc, float inv_count, float* out) {
    #pragma unroll
    for (int o = 16; o > 0; o >>= 1) acc += __shfl_down_sync(0xffffffffu, acc, o);
    __shared__ float sh[8];
    int lane = threadIdx.x & 31, wid = threadIdx.x >> 5;
    if (lane == 0) sh[wid] = acc;
    __syncthreads();
    if (wid == 0) {
        acc = (lane < (int)(blockDim.x >> 5)) ? sh[lane] : 0.0f;
        #pragma unroll
        for (int o = 4; o > 0; o >>= 1) acc += __shfl_down_sync(0xffffffffu, acc, o);
        if (lane == 0) atomicAdd(out, acc * inv_count);
    }
}

// unpack one u8-rgb word (1024+c trick) and accumulate with weight w (fp32)
__device__ __forceinline__ void u8_accum(unsigned word, float w,
                                         float& aR, float& aG, float& aB) {
    float2 rg = __half22float2(h2_from_u(__byte_perm(word, 0x64646464u, 0x4140)));
    float2 b_ = __half22float2(h2_from_u(__byte_perm(word, 0x64646464u, 0x4342)));
    aR = fmaf(w, rg.x, aR);
    aG = fmaf(w, rg.y, aG);
    aB = fmaf(w, b_.x, aB);
}

// ---------------- loss level0: u8-VP taps, 4 px/thread ----------------
__device__ __forceinline__ void loss_l0_body(int vtid,
                        const float* __restrict__ depth, const float* __restrict__ mask,
                        const float* __restrict__ rr,
                        const uint2* __restrict__ vpA, const uint2* __restrict__ vpB,
                        const float2* __restrict__ lonT, const float2* __restrict__ latT,
                        float* __restrict__ out) {
    constexpr int W = 1024, H = 512, HW = W*H;
    const float inv_count = 1.0f/(float)(BB*CC*L0);
    int pix = vtid * 4;
    int b = pix / HW;
    int p = pix % HW;
    int y = p / W, x = p % W;

    float RtL[24];
    {
        const float4* src = (const float4*)(g_Rt + b*24);
        #pragma unroll
        for (int q = 0; q < 6; q++) {
            float4 v = __ldg(src + q);
            RtL[q*4+0] = v.x; RtL[q*4+1] = v.y; RtL[q*4+2] = v.z; RtL[q*4+3] = v.w;
        }
    }

    float4 d4  = *(const float4*)(depth + pix);
    float2 la2 = __ldg(latT + y);
    float4 m0q = *(const float4*)(mask + ((size_t)(b*NF + 0))*HW + p);
    float4 m1q = *(const float4*)(mask + ((size_t)(b*NF + 1))*HW + p);
    float4 r0q = *(const float4*)(rr + ((size_t)b*CC + 0)*HW + p);
    float4 r1q = *(const float4*)(rr + ((size_t)b*CC + 1)*HW + p);
    float4 r2q = *(const float4*)(rr + ((size_t)b*CC + 2)*HW + p);
    float4 loA = __ldg((const float4*)(lonT + x));
    float4 loB = __ldg((const float4*)(lonT + x + 2));

    float acc = 0.0f;
    #pragma unroll
    for (int k = 0; k < 4; k++) {
        float d = getc(d4, k);
        float2 lo2;
        if (k == 0)      lo2 = make_float2(loA.x, loA.y);
        else if (k == 1) lo2 = make_float2(loA.z, loA.w);
        else if (k == 2) lo2 = make_float2(loB.x, loB.y);
        else             lo2 = make_float2(loB.z, loB.w);
        float px0 = d * (la2.y * lo2.x);
        float py0 = d * la2.x;
        float pz0 = d * (la2.y * lo2.y);
        float r0 = getc(r0q, k), r1 = getc(r1q, k), r2 = getc(r2q, k);
        #pragma unroll
        for (int n = 0; n < NF; n++) {
            int ix0, ix1, iy0; float fx, fy;
            project<W,H>(RtL + n*12, px0, py0, pz0, ix0, ix1, iy0, fx, fy);
            float wtA = (1.0f - fx) * (1.0f - fy);
            float wbA = (1.0f - fx) * fy;
            float wtC = fx * (1.0f - fy);
            float wbC = fx * fy;
            const uint2* base = ((n == 0) ? vpA : vpB) + (size_t)b*HW + (size_t)iy0*W;
            uint2 ta = __ldg(base + ix0);
            uint2 tc = __ldg(base + ix1);
            float aR = 0.f, aG = 0.f, aB = 0.f;
            u8_accum(ta.x, wtA, aR, aG, aB);
            u8_accum(ta.y, wbA, aR, aG, aB);
            u8_accum(tc.x, wtC, aR, aG, aB);
            u8_accum(tc.y, wbC, aR, aG, aB);
            // acc = 1024*Σw + Σw*c ; Σw == 1 (fp32), scale c back to [0,1]
            float vR = (aR - 1024.0f) * (1.0f/255.0f);
            float vG = (aG - 1024.0f) * (1.0f/255.0f);
            float vB = (aB - 1024.0f) * (1.0f/255.0f);
            float m = n ? getc(m1q, k) : getc(m0q, k);
            acc += m * (fabsf(r0 - vR) + fabsf(r1 - vG) + fabsf(r2 - vB));
        }
    }
    reduce_add(acc, inv_count, out);
}

// ---------------- loss small levels: H4 taps, 4 px/thread ----------------
template <int W, int H>
__device__ __forceinline__ void loss_body(int vtid,
                                          const float* __restrict__ depth,
                                          const float* __restrict__ mask,
                                          const float* __restrict__ rr,
                                          const H4* __restrict__ tgA,
                                          const H4* __restrict__ tgB,
                                          const float2* __restrict__ lonT,
                                          const float2* __restrict__ latT,
                                          float inv_count,
                                          float* __restrict__ out) {
    constexpr int HW = W * H;
    int pix = vtid * 4;
    int b = pix / HW;
    int p = pix % HW;
    int y = p / W, x = p % W;

    float RtL[24];
    {
        const float4* src = (const float4*)(g_Rt + b*24);
        #pragma unroll
        for (int q = 0; q < 6; q++) {
            float4 v = __ldg(src + q);
            RtL[q*4+0] = v.x; RtL[q*4+1] = v.y; RtL[q*4+2] = v.z; RtL[q*4+3] = v.w;
        }
    }

    float4 d4  = *(const float4*)(depth + pix);
    float2 la2 = __ldg(latT + y);
    float4 m0q = *(const float4*)(mask + ((size_t)(b*NF + 0))*HW + p);
    float4 m1q = *(const float4*)(mask + ((size_t)(b*NF + 1))*HW + p);
    float4 r0q = *(const float4*)(rr + ((size_t)b*CC + 0)*HW + p);
    float4 r1q = *(const float4*)(rr + ((size_t)b*CC + 1)*HW + p);
    float4 r2q = *(const float4*)(rr + ((size_t)b*CC + 2)*HW + p);
    float4 loA = __ldg((const float4*)(lonT + x));
    float4 loB = __ldg((const float4*)(lonT + x + 2));

    float acc = 0.0f;
    #pragma unroll
    for (int k = 0; k < 4; k++) {
        float d = getc(d4, k);
        float2 lo2;
        if (k == 0)      lo2 = make_float2(loA.x, loA.y);
        else if (k == 1) lo2 = make_float2(loA.z, loA.w);
        else if (k == 2) lo2 = make_float2(loB.x, loB.y);
        else             lo2 = make_float2(loB.z, loB.w);
        float px0 = d * (la2.y * lo2.x);
        float py0 = d * la2.x;
        float pz0 = d * (la2.y * lo2.y);
        float r0 = getc(r0q, k), r1 = getc(r1q, k), r2 = getc(r2q, k);
        #pragma unroll
        for (int n = 0; n < NF; n++) {
            int ix0, ix1, iy0; float fx, fy;
            project<W,H>(RtL + n*12, px0, py0, pz0, ix0, ix1, iy0, fx, fy);
            int iy1 = min(iy0 + 1, H - 1);
            __half2 hwa = __float2half2_rn((1.0f - fx) * (1.0f - fy));
            __half2 hwb = __float2half2_rn((1.0f - fx) * fy);
            __half2 hwc = __float2half2_rn(fx * (1.0f - fy));
            __half2 hwd = __float2half2_rn(fx * fy);
            const H4* base = ((n == 0) ? tgA : tgB) + (size_t)b*HW;
            const H4* row0 = base + (size_t)iy0*W;
            const H4* row1 = base + (size_t)iy1*W;
            H4 ta = row0[ix0];
            H4 tb = row1[ix0];
            H4 tc = row0[ix1];
            H4 td = row1[ix1];
            __half2 vrg = __hmul2(hwa, ta.rg);
            __half2 vbp = __hmul2(hwa, ta.bp);
            vrg = __hfma2(hwb, tb.rg, vrg);  vbp = __hfma2(hwb, tb.bp, vbp);
            vrg = __hfma2(hwc, tc.rg, vrg);  vbp = __hfma2(hwc, tc.bp, vbp);
            vrg = __hfma2(hwd, td.rg, vrg);  vbp = __hfma2(hwd, td.bp, vbp);
            float2 vf = __half22float2(vrg);
            float vb = __low2float(vbp);
            float m = n ? getc(m1q, k) : getc(m0q, k);
            acc += m * (fabsf(r0 - vf.x) + fabsf(r1 - vf.y) + fabsf(r2 - vb));
        }
    }
    reduce_add(acc, inv_count, out);
}

// ---------------- K4: all loss levels in one grid (4 px/thread) ----------------
__global__ void loss_all(const float* __restrict__ d0, const float* __restrict__ m0,
                         const float* __restrict__ d1, const float* __restrict__ m1,
                         const float* __restrict__ d2, const float* __restrict__ m2,
                         const float* __restrict__ d3, const float* __restrict__ m3,
                         const float* __restrict__ ref,
                         const float* __restrict__ rr1, const float* __restrict__ rr2,
                         const float* __restrict__ rr3,
                         const uint2* __restrict__ vp0, const uint2* __restrict__ vp1,
                         const H4* __restrict__ t01, const H4* __restrict__ t11,
                         const H4* __restrict__ t02, const H4* __restrict__ t12,
                         const H4* __restrict__ t03, const H4* __restrict__ t13,
                         const float2* __restrict__ lonT, const float2* __restrict__ latT,
                         float* __restrict__ out) {
    int bx = blockIdx.x;
    if (bx < 4096) {
        loss_l0_body(bx * 256 + threadIdx.x, d0, m0, ref, vp0, vp1, lonT, latT, out);
    } else if (bx < 5120) {
        loss_body<512,256>((bx - 4096) * 256 + threadIdx.x, d1, m1, rr1, t01, t11,
                           lonT + 1024, latT + 512, 1.0f/(float)(BB*CC*L1), out);
    } else if (bx < 5376) {
        loss_body<256,128>((bx - 5120) * 256 + threadIdx.x, d2, m2, rr2, t02, t12,
                           lonT + 1536, latT + 768, 1.0f/(float)(BB*CC*L2), out);
    } else {
        loss_body<128,64>((bx - 5376) * 256 + threadIdx.x, d3, m3, rr3, t03, t13,
                          lonT + 1792, latT + 896, 1.0f/(float)(BB*CC*L3), out);
    }
}

static inline int cdiv(int a, int b) { return (a + b - 1) / b; }

extern "C" void kernel_launch(void* const* d_in, const int* in_sizes, int n_in,
                              void* d_out, int out_size) {
    const float* ref   = (const float*)d_in[0];
    const float* dep[4] = {(const float*)d_in[1], (const float*)d_in[3],
                           (const float*)d_in[5], (const float*)d_in[7]};
    const float* msk[4] = {(const float*)d_in[2], (const float*)d_in[4],
                           (const float*)d_in[6], (const float*)d_in[8]};
    const float* tgt0  = (const float*)d_in[9];
    const float* tgt1  = (const float*)d_in[10];
    const float* pose  = (const float*)d_in[11];
    float* out = (float*)d_out;

    float *rr1, *rr2, *rr3;
    uint2 *vp0, *vp1;
    H4 *t01, *t02, *t03, *t11, *t12, *t13;
    float2 *lonT, *latT;
    cudaGetSymbolAddress((void**)&rr1, g_rr1);
    cudaGetSymbolAddress((void**)&rr2, g_rr2);
    cudaGetSymbolAddress((void**)&rr3, g_rr3);
    cudaGetSymbolAddress((void**)&vp0, g_vp0);
    cudaGetSymbolAddress((void**)&vp1, g_vp1);
    cudaGetSymbolAddress((void**)&t01, g_t0_1);
    cudaGetSymbolAddress((void**)&t02, g_t0_2);
    cudaGetSymbolAddress((void**)&t03, g_t0_3);
    cudaGetSymbolAddress((void**)&t11, g_t1_1);
    cudaGetSymbolAddress((void**)&t12, g_t1_2);
    cudaGetSymbolAddress((void**)&t13, g_t1_3);
    cudaGetSymbolAddress((void**)&lonT, g_lon);
    cudaGetSymbolAddress((void**)&latT, g_lat);

    const int T = 256;

    setup_kernel<<<12, T>>>(pose, out);                                    // 1
    build01<<<16384, T>>>(tgt0, tgt1, ref, vp0, vp1, t01, t11, rr1);       // 2
    build23<<<1280, T>>>(t01, t11, t02, t12, t03, t13, rr1, rr2, rr3);     // 3
    loss_all<<<5440, T>>>(dep[0], msk[0], dep[1], msk[1], dep[2], msk[2],  // 4 (profiled)
                          dep[3], msk[3], ref, rr1, rr2, rr3, vp0, vp1,
                          t01, t11, t02, t12, t03, t13, lonT, latT, out);
}